// round 1
// baseline (speedup 1.0000x reference)
#include <cuda_runtime.h>

// Network24: tiny 2->2->1 synapse MLP, pointwise over B rows.
// Pure HBM-streaming: 12 B/row. Vectorized 4 rows/thread.

__device__ __forceinline__ float fpow(float x, float p) {
    // powers are uniform scalars across the grid; p==1 branch is warp-uniform
    return (p == 1.0f) ? x : __powf(x, p);
}

__device__ __forceinline__ float fsig(float z) {
    return 1.0f / (1.0f + __expf(-z));
}

struct Params {
    float w00, w01, w10, w11;   // fc1_tw[i][j][0]
    float p00, p01, p10, p11;   // fc1_power[i][j]
    float b0, b1;               // fc1_bias
    float m0, m1, m2, m3;       // m4_tw[k][0]
    float q0, q1, q2, q3;       // m4_power
    float bias3;
};

__device__ __forceinline__ float net_row(float x0, float x1, const Params& P) {
    float h0 = fsig(P.w00 * fpow(x0, P.p00) + P.w01 * fpow(x1, P.p01) + P.b0);
    float h1 = fsig(P.w10 * fpow(x0, P.p10) + P.w11 * fpow(x1, P.p11) + P.b1);
    float s1 = P.m0 * fpow(h0, P.q0);
    float s2 = P.m1 * fpow(h1, P.q1);
    float p1 = P.m2 * fpow(h0, P.q2);
    float p2 = P.m3 * fpow(h1, P.q3);
    return fsig(s1 + s2 + p1 * p2 + P.bias3);
}

__device__ __forceinline__ Params load_params(
    const float* __restrict__ fc1_tw, const float* __restrict__ fc1_power,
    const float* __restrict__ fc1_bias, const float* __restrict__ m4_tw,
    const float* __restrict__ m4_power, const float* __restrict__ m4_bias3) {
    Params P;
    // fc1_tw shape (2,2,3): [i][j][0] -> i*6 + j*3
    P.w00 = fc1_tw[0]; P.w01 = fc1_tw[3]; P.w10 = fc1_tw[6]; P.w11 = fc1_tw[9];
    P.p00 = fc1_power[0]; P.p01 = fc1_power[1];
    P.p10 = fc1_power[2]; P.p11 = fc1_power[3];
    P.b0 = fc1_bias[0]; P.b1 = fc1_bias[1];
    // m4_tw shape (4,3): [k][0] -> k*3
    P.m0 = m4_tw[0]; P.m1 = m4_tw[3]; P.m2 = m4_tw[6]; P.m3 = m4_tw[9];
    P.q0 = m4_power[0]; P.q1 = m4_power[1]; P.q2 = m4_power[2]; P.q3 = m4_power[3];
    P.bias3 = m4_bias3[0];
    return P;
}

__global__ void __launch_bounds__(256)
net24_vec4_kernel(const float4* __restrict__ x4,   // 2 float4 = 4 rows
                  const float* __restrict__ fc1_tw,
                  const float* __restrict__ fc1_power,
                  const float* __restrict__ fc1_bias,
                  const float* __restrict__ m4_tw,
                  const float* __restrict__ m4_power,
                  const float* __restrict__ m4_bias3,
                  float4* __restrict__ out4,
                  int n4)                            // number of 4-row groups
{
    int i = blockIdx.x * blockDim.x + threadIdx.x;
    if (i >= n4) return;

    // Two consecutive 16B loads = rows 4i..4i+3 (x is [B,2] row-major)
    float4 a = x4[2 * i];
    float4 b = x4[2 * i + 1];

    Params P = load_params(fc1_tw, fc1_power, fc1_bias, m4_tw, m4_power, m4_bias3);

    float4 r;
    r.x = net_row(a.x, a.y, P);
    r.y = net_row(a.z, a.w, P);
    r.z = net_row(b.x, b.y, P);
    r.w = net_row(b.z, b.w, P);
    out4[i] = r;
}

__global__ void net24_tail_kernel(const float2* __restrict__ x2,
                                  const float* __restrict__ fc1_tw,
                                  const float* __restrict__ fc1_power,
                                  const float* __restrict__ fc1_bias,
                                  const float* __restrict__ m4_tw,
                                  const float* __restrict__ m4_power,
                                  const float* __restrict__ m4_bias3,
                                  float* __restrict__ out,
                                  int start, int n)
{
    int i = start + blockIdx.x * blockDim.x + threadIdx.x;
    if (i >= n) return;
    Params P = load_params(fc1_tw, fc1_power, fc1_bias, m4_tw, m4_power, m4_bias3);
    float2 v = x2[i];
    out[i] = net_row(v.x, v.y, P);
}

extern "C" void kernel_launch(void* const* d_in, const int* in_sizes, int n_in,
                              void* d_out, int out_size)
{
    const float* x         = (const float*)d_in[0];
    const float* fc1_tw    = (const float*)d_in[1];
    const float* fc1_power = (const float*)d_in[2];
    const float* fc1_bias  = (const float*)d_in[3];
    const float* m4_tw     = (const float*)d_in[4];
    const float* m4_power  = (const float*)d_in[5];
    const float* m4_bias3  = (const float*)d_in[6];
    float* out = (float*)d_out;

    int B  = in_sizes[0] / 2;   // rows
    int n4 = B / 4;             // full 4-row groups
    int rem_start = n4 * 4;

    if (n4 > 0) {
        int threads = 256;
        int blocks  = (n4 + threads - 1) / threads;
        net24_vec4_kernel<<<blocks, threads>>>(
            (const float4*)x, fc1_tw, fc1_power, fc1_bias,
            m4_tw, m4_power, m4_bias3, (float4*)out, n4);
    }
    if (rem_start < B) {
        int rem = B - rem_start;
        net24_tail_kernel<<<(rem + 127) / 128, 128>>>(
            (const float2*)x, fc1_tw, fc1_power, fc1_bias,
            m4_tw, m4_power, m4_bias3, out, rem_start, B);
    }
}

// round 2
// speedup vs baseline: 1.3686x; 1.3686x over previous
#include <cuda_runtime.h>

// Network24: tiny 2->2->1 synapse MLP, pointwise over B rows.
// 12 B/row HBM traffic -> DRAM-streaming target.
// R2: 8 rows/thread (4x LDG.128 + 2x STG.128), MUFU.TANH sigmoid.

__device__ __forceinline__ float fpow(float x, float p) {
    // powers are grid-uniform scalars; p==1 branch is warp-uniform
    return (p == 1.0f) ? x : __powf(x, p);
}

__device__ __forceinline__ float fsig(float z) {
    // sigmoid(z) = 0.5*tanh(z/2) + 0.5  -- single MUFU.TANH
    float t;
    asm("tanh.approx.f32 %0, %1;" : "=f"(t) : "f"(0.5f * z));
    return fmaf(0.5f, t, 0.5f);
}

struct Params {
    float w00, w01, w10, w11;   // fc1_tw[i][j][0]
    float p00, p01, p10, p11;   // fc1_power[i][j]
    float b0, b1;               // fc1_bias
    float m0, m1, m2, m3;       // m4_tw[k][0]
    float q0, q1, q2, q3;       // m4_power
    float bias3;
};

__device__ __forceinline__ float net_row(float x0, float x1, const Params& P) {
    float h0 = fsig(fmaf(P.w00, fpow(x0, P.p00), fmaf(P.w01, fpow(x1, P.p01), P.b0)));
    float h1 = fsig(fmaf(P.w10, fpow(x0, P.p10), fmaf(P.w11, fpow(x1, P.p11), P.b1)));
    float s1 = P.m0 * fpow(h0, P.q0);
    float s2 = P.m1 * fpow(h1, P.q1);
    float p1 = P.m2 * fpow(h0, P.q2);
    float p2 = P.m3 * fpow(h1, P.q3);
    return fsig(fmaf(p1, p2, s1 + s2) + P.bias3);
}

__device__ __forceinline__ Params load_params(
    const float* __restrict__ fc1_tw, const float* __restrict__ fc1_power,
    const float* __restrict__ fc1_bias, const float* __restrict__ m4_tw,
    const float* __restrict__ m4_power, const float* __restrict__ m4_bias3) {
    Params P;
    // fc1_tw shape (2,2,3): [i][j][0] -> i*6 + j*3
    P.w00 = __ldg(fc1_tw + 0); P.w01 = __ldg(fc1_tw + 3);
    P.w10 = __ldg(fc1_tw + 6); P.w11 = __ldg(fc1_tw + 9);
    P.p00 = __ldg(fc1_power + 0); P.p01 = __ldg(fc1_power + 1);
    P.p10 = __ldg(fc1_power + 2); P.p11 = __ldg(fc1_power + 3);
    P.b0 = __ldg(fc1_bias + 0); P.b1 = __ldg(fc1_bias + 1);
    // m4_tw shape (4,3): [k][0] -> k*3
    P.m0 = __ldg(m4_tw + 0); P.m1 = __ldg(m4_tw + 3);
    P.m2 = __ldg(m4_tw + 6); P.m3 = __ldg(m4_tw + 9);
    P.q0 = __ldg(m4_power + 0); P.q1 = __ldg(m4_power + 1);
    P.q2 = __ldg(m4_power + 2); P.q3 = __ldg(m4_power + 3);
    P.bias3 = __ldg(m4_bias3);
    return P;
}

__global__ void __launch_bounds__(256)
net24_vec8_kernel(const float4* __restrict__ x4,   // 4 float4 = 8 rows
                  const float* __restrict__ fc1_tw,
                  const float* __restrict__ fc1_power,
                  const float* __restrict__ fc1_bias,
                  const float* __restrict__ m4_tw,
                  const float* __restrict__ m4_power,
                  const float* __restrict__ m4_bias3,
                  float4* __restrict__ out4,
                  int n8)                            // number of 8-row groups
{
    int i = blockIdx.x * blockDim.x + threadIdx.x;
    if (i >= n8) return;

    // Front-batch the 4 wide loads (rows 8i..8i+7; x is [B,2] row-major)
    float4 a = x4[4 * i + 0];
    float4 b = x4[4 * i + 1];
    float4 c = x4[4 * i + 2];
    float4 d = x4[4 * i + 3];

    Params P = load_params(fc1_tw, fc1_power, fc1_bias, m4_tw, m4_power, m4_bias3);

    float4 r0, r1;
    r0.x = net_row(a.x, a.y, P);
    r0.y = net_row(a.z, a.w, P);
    r0.z = net_row(b.x, b.y, P);
    r0.w = net_row(b.z, b.w, P);
    r1.x = net_row(c.x, c.y, P);
    r1.y = net_row(c.z, c.w, P);
    r1.z = net_row(d.x, d.y, P);
    r1.w = net_row(d.z, d.w, P);

    out4[2 * i + 0] = r0;
    out4[2 * i + 1] = r1;
}

__global__ void net24_tail_kernel(const float2* __restrict__ x2,
                                  const float* __restrict__ fc1_tw,
                                  const float* __restrict__ fc1_power,
                                  const float* __restrict__ fc1_bias,
                                  const float* __restrict__ m4_tw,
                                  const float* __restrict__ m4_power,
                                  const float* __restrict__ m4_bias3,
                                  float* __restrict__ out,
                                  int start, int n)
{
    int i = start + blockIdx.x * blockDim.x + threadIdx.x;
    if (i >= n) return;
    Params P = load_params(fc1_tw, fc1_power, fc1_bias, m4_tw, m4_power, m4_bias3);
    float2 v = x2[i];
    out[i] = net_row(v.x, v.y, P);
}

extern "C" void kernel_launch(void* const* d_in, const int* in_sizes, int n_in,
                              void* d_out, int out_size)
{
    const float* x         = (const float*)d_in[0];
    const float* fc1_tw    = (const float*)d_in[1];
    const float* fc1_power = (const float*)d_in[2];
    const float* fc1_bias  = (const float*)d_in[3];
    const float* m4_tw     = (const float*)d_in[4];
    const float* m4_power  = (const float*)d_in[5];
    const float* m4_bias3  = (const float*)d_in[6];
    float* out = (float*)d_out;

    int B  = in_sizes[0] / 2;   // rows
    int n8 = B / 8;             // full 8-row groups
    int rem_start = n8 * 8;

    if (n8 > 0) {
        int threads = 256;
        int blocks  = (n8 + threads - 1) / threads;
        net24_vec8_kernel<<<blocks, threads>>>(
            (const float4*)x, fc1_tw, fc1_power, fc1_bias,
            m4_tw, m4_power, m4_bias3, (float4*)out, n8);
    }
    if (rem_start < B) {
        int rem = B - rem_start;
        net24_tail_kernel<<<(rem + 127) / 128, 128>>>(
            (const float2*)x, fc1_tw, fc1_power, fc1_bias,
            m4_tw, m4_power, m4_bias3, out, rem_start, B);
    }
}